// round 1
// baseline (speedup 1.0000x reference)
#include <cuda_runtime.h>
#include <math.h>

// Problem constants (fixed by the reference)
#define HID     50
#define NG      200      // 4*HID
#define IN0     17       // state_dim + 1
#define SDIM    16
#define TSTEPS  128
#define FC1N    25       // HIDDEN/2

// Tiling
#define ROWS      64     // batch rows per block
#define NTHREADS  400    // 8 row-groups * 50 hidden units
#define RPT       8      // rows per thread

// Padded strides for conflict-free smem weight reads
#define WI_STRIDE  17    // gcd(17,32)=1 -> conflict free
#define WH_STRIDE  51    // gcd(51%32=19,32)=1 -> conflict free
#define FC1_STRIDE 51

__device__ __forceinline__ float sigmoidf_(float x) {
    return 1.0f / (1.0f + expf(-x));
}

__global__ __launch_bounds__(NTHREADS, 1)
void kozyra_lstm_kernel(const float* __restrict__ features,
                        const float* __restrict__ w_ih0, const float* __restrict__ w_hh0,
                        const float* __restrict__ b0,
                        const float* __restrict__ w_ih1, const float* __restrict__ w_hh1,
                        const float* __restrict__ b1,
                        const float* __restrict__ w_fc1, const float* __restrict__ b_fc1,
                        const float* __restrict__ w_fc2, const float* __restrict__ b_fc2,
                        float* __restrict__ out)
{
    extern __shared__ float sm[];
    float* s_wih0 = sm;                              // 200*17  = 3400
    float* s_whh0 = s_wih0 + NG * WI_STRIDE;         // 200*51  = 10200
    float* s_wih1 = s_whh0 + NG * WH_STRIDE;         // 10200
    float* s_whh1 = s_wih1 + NG * WH_STRIDE;         // 10200
    float* s_fc1  = s_whh1 + NG * WH_STRIDE;         // 25*51   = 1275
    float* s_fc2  = s_fc1  + FC1N * FC1_STRIDE;      // 25
    float* s_b0   = s_fc2  + FC1N;                   // 200
    float* s_b1   = s_b0   + NG;                     // 200
    float* s_bfc1 = s_b1   + NG;                     // 25
    float* s_bfc2 = s_bfc1 + FC1N;                   // 1
    float* s_x    = s_bfc2 + 1;                      // 64*17   = 1088
    float* s_h0   = s_x    + ROWS * IN0;             // 64*50   = 3200
    float* s_h1   = s_h0   + ROWS * HID;             // 3200
    float* s_act  = s_h1   + ROWS * HID;             // 64*25   = 1600
    float* s_delta= s_act  + ROWS * FC1N;            // 64
    // total = 44878 floats = 179512 bytes

    const int tid  = threadIdx.x;
    const int brow = blockIdx.x * ROWS;

    // ---- One-time: stage weights into shared memory ----
    for (int i = tid; i < NG * IN0; i += NTHREADS) s_wih0[i] = w_ih0[i];
    for (int i = tid; i < NG * HID; i += NTHREADS) {
        int g = i / HID, k = i % HID;
        s_whh0[g * WH_STRIDE + k] = w_hh0[i];
        s_wih1[g * WH_STRIDE + k] = w_ih1[i];
        s_whh1[g * WH_STRIDE + k] = w_hh1[i];
    }
    for (int i = tid; i < FC1N * HID; i += NTHREADS) {
        int n = i / HID, k = i % HID;
        s_fc1[n * FC1_STRIDE + k] = w_fc1[i];
    }
    for (int i = tid; i < FC1N; i += NTHREADS) { s_fc2[i] = w_fc2[i]; s_bfc1[i] = b_fc1[i]; }
    for (int i = tid; i < NG;   i += NTHREADS) { s_b0[i] = b0[i]; s_b1[i] = b1[i]; }
    if (tid == 0) s_bfc2[0] = b_fc2[0];

    // ---- Init recurrent state ----
    for (int i = tid; i < ROWS * HID; i += NTHREADS) { s_h0[i] = 0.0f; s_h1[i] = 0.0f; }
    for (int i = tid; i < ROWS; i += NTHREADS) s_delta[i] = 0.0f;
    __syncthreads();

    const int j  = tid % HID;    // hidden unit (valid: tid < 400)
    const int rg = tid / HID;    // row group 0..7
    const int r0 = rg * RPT;

    float c0[RPT], c1[RPT], h0n[RPT], h1n[RPT];
    #pragma unroll
    for (int i = 0; i < RPT; i++) { c0[i] = 0.0f; c1[i] = 0.0f; }

    const float bi0 = s_b0[j],        bf0 = s_b0[HID + j];
    const float bg0 = s_b0[2*HID + j], bo0 = s_b0[3*HID + j];
    const float bi1 = s_b1[j],        bf1 = s_b1[HID + j];
    const float bg1 = s_b1[2*HID + j], bo1 = s_b1[3*HID + j];

    for (int t = 0; t < TSTEPS; t++) {
        // ---- Build x = [features[:,t,:], prev_delta] in shared ----
        for (int i = tid; i < ROWS * SDIM; i += NTHREADS) {
            int r = i / SDIM, s = i % SDIM;
            s_x[r * IN0 + s] =
                features[(size_t)(brow + r) * (TSTEPS * SDIM) + (size_t)t * SDIM + s];
        }
        for (int r = tid; r < ROWS; r += NTHREADS) s_x[r * IN0 + SDIM] = s_delta[r];
        __syncthreads();

        // ---- Layer-0 gates: x @ w_ih0^T + h0 @ w_hh0^T + b0 ----
        float ai[RPT], af[RPT], ag[RPT], ao[RPT];
        #pragma unroll
        for (int i = 0; i < RPT; i++) { ai[i] = bi0; af[i] = bf0; ag[i] = bg0; ao[i] = bo0; }

        for (int k = 0; k < IN0; k++) {
            float wi = s_wih0[j * IN0 + k];
            float wf = s_wih0[(HID + j) * IN0 + k];
            float wg = s_wih0[(2*HID + j) * IN0 + k];
            float wo = s_wih0[(3*HID + j) * IN0 + k];
            #pragma unroll
            for (int i = 0; i < RPT; i++) {
                float xv = s_x[(r0 + i) * IN0 + k];
                ai[i] = fmaf(wi, xv, ai[i]);
                af[i] = fmaf(wf, xv, af[i]);
                ag[i] = fmaf(wg, xv, ag[i]);
                ao[i] = fmaf(wo, xv, ao[i]);
            }
        }
        for (int k = 0; k < HID; k++) {
            float wi = s_whh0[j * WH_STRIDE + k];
            float wf = s_whh0[(HID + j) * WH_STRIDE + k];
            float wg = s_whh0[(2*HID + j) * WH_STRIDE + k];
            float wo = s_whh0[(3*HID + j) * WH_STRIDE + k];
            #pragma unroll
            for (int i = 0; i < RPT; i++) {
                float hv = s_h0[(r0 + i) * HID + k];
                ai[i] = fmaf(wi, hv, ai[i]);
                af[i] = fmaf(wf, hv, af[i]);
                ag[i] = fmaf(wg, hv, ag[i]);
                ao[i] = fmaf(wo, hv, ao[i]);
            }
        }
        #pragma unroll
        for (int i = 0; i < RPT; i++) {
            float iv = sigmoidf_(ai[i]);
            float fv = sigmoidf_(af[i]);
            float gv = tanhf(ag[i]);
            float ov = sigmoidf_(ao[i]);
            c0[i]  = fv * c0[i] + iv * gv;
            h0n[i] = ov * tanhf(c0[i]);
        }
        __syncthreads();   // all readers of old s_h0 done
        #pragma unroll
        for (int i = 0; i < RPT; i++) s_h0[(r0 + i) * HID + j] = h0n[i];
        __syncthreads();   // new s_h0 visible

        // ---- Layer-1 gates: h0 @ w_ih1^T + h1 @ w_hh1^T + b1 ----
        #pragma unroll
        for (int i = 0; i < RPT; i++) { ai[i] = bi1; af[i] = bf1; ag[i] = bg1; ao[i] = bo1; }

        for (int k = 0; k < HID; k++) {
            float wi = s_wih1[j * WH_STRIDE + k];
            float wf = s_wih1[(HID + j) * WH_STRIDE + k];
            float wg = s_wih1[(2*HID + j) * WH_STRIDE + k];
            float wo = s_wih1[(3*HID + j) * WH_STRIDE + k];
            #pragma unroll
            for (int i = 0; i < RPT; i++) {
                float hv = s_h0[(r0 + i) * HID + k];
                ai[i] = fmaf(wi, hv, ai[i]);
                af[i] = fmaf(wf, hv, af[i]);
                ag[i] = fmaf(wg, hv, ag[i]);
                ao[i] = fmaf(wo, hv, ao[i]);
            }
        }
        for (int k = 0; k < HID; k++) {
            float wi = s_whh1[j * WH_STRIDE + k];
            float wf = s_whh1[(HID + j) * WH_STRIDE + k];
            float wg = s_whh1[(2*HID + j) * WH_STRIDE + k];
            float wo = s_whh1[(3*HID + j) * WH_STRIDE + k];
            #pragma unroll
            for (int i = 0; i < RPT; i++) {
                float hv = s_h1[(r0 + i) * HID + k];
                ai[i] = fmaf(wi, hv, ai[i]);
                af[i] = fmaf(wf, hv, af[i]);
                ag[i] = fmaf(wg, hv, ag[i]);
                ao[i] = fmaf(wo, hv, ao[i]);
            }
        }
        #pragma unroll
        for (int i = 0; i < RPT; i++) {
            float iv = sigmoidf_(ai[i]);
            float fv = sigmoidf_(af[i]);
            float gv = tanhf(ag[i]);
            float ov = sigmoidf_(ao[i]);
            c1[i]  = fv * c1[i] + iv * gv;
            h1n[i] = ov * tanhf(c1[i]);
        }
        __syncthreads();   // all readers of old s_h1 done
        #pragma unroll
        for (int i = 0; i < RPT; i++) s_h1[(r0 + i) * HID + j] = h1n[i];
        __syncthreads();   // new s_h1 visible

        // ---- fc1: relu(h1 @ w_fc1^T + b_fc1), 64x25 outputs ----
        for (int task = tid; task < ROWS * FC1N; task += NTHREADS) {
            int r = task / FC1N, n = task % FC1N;
            float acc = s_bfc1[n];
            const float* wrow = &s_fc1[n * FC1_STRIDE];
            const float* hrow = &s_h1[r * HID];
            #pragma unroll 10
            for (int k = 0; k < HID; k++) acc = fmaf(wrow[k], hrow[k], acc);
            s_act[task] = acc > 0.0f ? acc : 0.0f;
        }
        __syncthreads();

        // ---- fc2: delta = act @ w_fc2^T + b_fc2, one scalar per row ----
        if (tid < ROWS) {
            float acc = s_bfc2[0];
            const float* arow = &s_act[tid * FC1N];
            #pragma unroll
            for (int k = 0; k < FC1N; k++) acc = fmaf(s_fc2[k], arow[k], acc);
            s_delta[tid] = acc;
            out[(size_t)(brow + tid) * TSTEPS + t] = acc;
        }
        __syncthreads();
    }
}

extern "C" void kernel_launch(void* const* d_in, const int* in_sizes, int n_in,
                              void* d_out, int out_size)
{
    const float* features = (const float*)d_in[0];
    const float* w_ih0    = (const float*)d_in[1];
    const float* w_hh0    = (const float*)d_in[2];
    const float* b0       = (const float*)d_in[3];
    const float* w_ih1    = (const float*)d_in[4];
    const float* w_hh1    = (const float*)d_in[5];
    const float* b1       = (const float*)d_in[6];
    const float* w_fc1    = (const float*)d_in[7];
    const float* b_fc1    = (const float*)d_in[8];
    const float* w_fc2    = (const float*)d_in[9];
    const float* b_fc2    = (const float*)d_in[10];
    float* out = (float*)d_out;

    const int batch = in_sizes[0] / (TSTEPS * SDIM);   // 8192
    const int nblocks = batch / ROWS;                  // 128

    const size_t smem_bytes = 44878 * sizeof(float);   // 179512 B
    cudaFuncSetAttribute(kozyra_lstm_kernel,
                         cudaFuncAttributeMaxDynamicSharedMemorySize,
                         (int)smem_bytes);

    kozyra_lstm_kernel<<<nblocks, NTHREADS, smem_bytes>>>(
        features, w_ih0, w_hh0, b0, w_ih1, w_hh1, b1,
        w_fc1, b_fc1, w_fc2, b_fc2, out);
}

// round 2
// speedup vs baseline: 2.2451x; 2.2451x over previous
#include <cuda_runtime.h>

// Problem constants
#define HID     50
#define NG      200
#define IN0     17
#define SDIM    16
#define TSTEPS  128
#define FC1N    25

// Tiling
#define ROWS      64
#define NTHREADS  400
#define RPT       8
#define NPAIR     4      // RPT/2 float2 pairs

// Strides (floats)
#define WI_STRIDE  17
#define WH_STRIDE  51
#define FC1_STRIDE 51
#define TSTRIDE    66    // transposed state stride: 66%32=2 -> conflict-free float2

typedef unsigned long long ull;

__device__ __forceinline__ ull pack2(float a, float b) {
    ull r; asm("mov.b64 %0,{%1,%2};" : "=l"(r) : "f"(a), "f"(b)); return r;
}
__device__ __forceinline__ float2 unpk(ull v) {
    float2 f; asm("mov.b64 {%0,%1},%2;" : "=f"(f.x), "=f"(f.y) : "l"(v)); return f;
}
__device__ __forceinline__ void fma2(ull& d, ull a, ull b) {
    asm("fma.rn.f32x2 %0,%1,%2,%0;" : "+l"(d) : "l"(a), "l"(b));
}
__device__ __forceinline__ float tanh_a(float x) {
    float y; asm("tanh.approx.f32 %0,%1;" : "=f"(y) : "f"(x)); return y;
}
__device__ __forceinline__ float sig_a(float x) {
    return fmaf(tanh_a(0.5f * x), 0.5f, 0.5f);
}

// Shared memory layout (float offsets, all even for 8B alignment)
#define OFF_WIH0   0                       // 200*17 = 3400
#define OFF_WHH0   3400                    // 200*51 = 10200
#define OFF_WIH1   13600                   // 10200
#define OFF_WHH1   23800                   // 10200
#define OFF_FC1    34000                   // 25*51 = 1275
#define OFF_FC2    35276                   // 25
#define OFF_B0     35302                   // 200
#define OFF_B1     35502                   // 200
#define OFF_BFC1   35702                   // 25
#define OFF_BFC2   35728                   // 2
#define OFF_X      35730                   // 17*66 = 1122 (transposed)
#define OFF_H0     36852                   // 2 * 50*66 = 6600 (double buffered, transposed)
#define OFF_H1     43452                   // 6600
#define OFF_ACT    50052                   // 64*25 = 1600
#define OFF_DELTA  51652                   // 64
#define SMEM_FLOATS 51716                  // 206864 bytes

__global__ __launch_bounds__(NTHREADS, 1)
void kozyra_lstm_kernel(const float* __restrict__ features,
                        const float* __restrict__ w_ih0, const float* __restrict__ w_hh0,
                        const float* __restrict__ b0,
                        const float* __restrict__ w_ih1, const float* __restrict__ w_hh1,
                        const float* __restrict__ b1,
                        const float* __restrict__ w_fc1, const float* __restrict__ b_fc1,
                        const float* __restrict__ w_fc2, const float* __restrict__ b_fc2,
                        float* __restrict__ out)
{
    extern __shared__ float sm[];
    float* s_wih0 = sm + OFF_WIH0;
    float* s_whh0 = sm + OFF_WHH0;
    float* s_wih1 = sm + OFF_WIH1;
    float* s_whh1 = sm + OFF_WHH1;
    float* s_fc1  = sm + OFF_FC1;
    float* s_fc2  = sm + OFF_FC2;
    float* s_b0   = sm + OFF_B0;
    float* s_b1   = sm + OFF_B1;
    float* s_bfc1 = sm + OFF_BFC1;
    float* s_bfc2 = sm + OFF_BFC2;
    float* s_x    = sm + OFF_X;      // [IN0][TSTRIDE]
    float* s_h0b  = sm + OFF_H0;     // 2 x [HID][TSTRIDE]
    float* s_h1b  = sm + OFF_H1;
    float* s_act  = sm + OFF_ACT;    // [ROWS][FC1N]
    float* s_delta= sm + OFF_DELTA;  // [ROWS]

    const int tid  = threadIdx.x;
    const int brow = blockIdx.x * ROWS;

    // ---- Stage weights ----
    for (int i = tid; i < NG * IN0; i += NTHREADS) s_wih0[i] = w_ih0[i];
    for (int i = tid; i < NG * HID; i += NTHREADS) {
        int g = i / HID, k = i % HID;
        s_whh0[g * WH_STRIDE + k] = w_hh0[i];
        s_wih1[g * WH_STRIDE + k] = w_ih1[i];
        s_whh1[g * WH_STRIDE + k] = w_hh1[i];
    }
    for (int i = tid; i < FC1N * HID; i += NTHREADS) {
        int n = i / HID, k = i % HID;
        s_fc1[n * FC1_STRIDE + k] = w_fc1[i];
    }
    for (int i = tid; i < FC1N; i += NTHREADS) { s_fc2[i] = w_fc2[i]; s_bfc1[i] = b_fc1[i]; }
    for (int i = tid; i < NG;   i += NTHREADS) { s_b0[i] = b0[i]; s_b1[i] = b1[i]; }
    if (tid == 0) s_bfc2[0] = b_fc2[0];

    // ---- Init state (both buffers) ----
    for (int i = tid; i < 2 * HID * TSTRIDE; i += NTHREADS) { s_h0b[i] = 0.0f; s_h1b[i] = 0.0f; }
    for (int i = tid; i < ROWS; i += NTHREADS) s_delta[i] = 0.0f;
    __syncthreads();

    const int j  = tid % HID;     // hidden unit
    const int rg = tid / HID;     // row group 0..7
    const int r0 = rg * RPT;      // even

    float c0x[NPAIR], c0y[NPAIR], c1x[NPAIR], c1y[NPAIR];
    #pragma unroll
    for (int p = 0; p < NPAIR; p++) { c0x[p]=c0y[p]=c1x[p]=c1y[p]=0.0f; }

    const ull bi0 = pack2(s_b0[j], s_b0[j]);
    const ull bf0 = pack2(s_b0[HID + j], s_b0[HID + j]);
    const ull bg0 = pack2(s_b0[2*HID + j], s_b0[2*HID + j]);
    const ull bo0 = pack2(s_b0[3*HID + j], s_b0[3*HID + j]);
    const ull bi1 = pack2(s_b1[j], s_b1[j]);
    const ull bf1 = pack2(s_b1[HID + j], s_b1[HID + j]);
    const ull bg1 = pack2(s_b1[2*HID + j], s_b1[2*HID + j]);
    const ull bo1 = pack2(s_b1[3*HID + j], s_b1[3*HID + j]);

    const float* wih0_i = &s_wih0[j * IN0];
    const float* wih0_f = &s_wih0[(HID + j) * IN0];
    const float* wih0_g = &s_wih0[(2*HID + j) * IN0];
    const float* wih0_o = &s_wih0[(3*HID + j) * IN0];
    const float* whh0_i = &s_whh0[j * WH_STRIDE];
    const float* whh0_f = &s_whh0[(HID + j) * WH_STRIDE];
    const float* whh0_g = &s_whh0[(2*HID + j) * WH_STRIDE];
    const float* whh0_o = &s_whh0[(3*HID + j) * WH_STRIDE];
    const float* wih1_i = &s_wih1[j * WH_STRIDE];
    const float* wih1_f = &s_wih1[(HID + j) * WH_STRIDE];
    const float* wih1_g = &s_wih1[(2*HID + j) * WH_STRIDE];
    const float* wih1_o = &s_wih1[(3*HID + j) * WH_STRIDE];
    const float* whh1_i = &s_whh1[j * WH_STRIDE];
    const float* whh1_f = &s_whh1[(HID + j) * WH_STRIDE];
    const float* whh1_g = &s_whh1[(2*HID + j) * WH_STRIDE];
    const float* whh1_o = &s_whh1[(3*HID + j) * WH_STRIDE];

    const float* fbase = features + (size_t)brow * (TSTEPS * SDIM);

    for (int t = 0; t < TSTEPS; t++) {
        const int p  = t & 1;       // read buffer
        const int q  = p ^ 1;       // write buffer
        float* h0r = s_h0b + p * (HID * TSTRIDE);
        float* h0w = s_h0b + q * (HID * TSTRIDE);
        float* h1r = s_h1b + p * (HID * TSTRIDE);
        float* h1w = s_h1b + q * (HID * TSTRIDE);

        // ---- Build transposed x: s_x[s][r] ----
        for (int i = tid; i < ROWS * SDIM; i += NTHREADS) {
            int r = i / SDIM, s = i % SDIM;
            s_x[s * TSTRIDE + r] = fbase[(size_t)r * (TSTEPS * SDIM) + t * SDIM + s];
        }
        for (int r = tid; r < ROWS; r += NTHREADS) s_x[SDIM * TSTRIDE + r] = s_delta[r];
        __syncthreads();

        // ================= Layer 0 =================
        ull ai[NPAIR], af[NPAIR], ag[NPAIR], ao[NPAIR];
        #pragma unroll
        for (int pp = 0; pp < NPAIR; pp++) { ai[pp]=bi0; af[pp]=bf0; ag[pp]=bg0; ao[pp]=bo0; }

        #pragma unroll 4
        for (int k = 0; k < IN0; k++) {
            ull wi = pack2(wih0_i[k], wih0_i[k]);
            ull wf = pack2(wih0_f[k], wih0_f[k]);
            ull wg = pack2(wih0_g[k], wih0_g[k]);
            ull wo = pack2(wih0_o[k], wih0_o[k]);
            #pragma unroll
            for (int pp = 0; pp < NPAIR; pp++) {
                ull xv = *(const ull*)&s_x[k * TSTRIDE + r0 + 2*pp];
                fma2(ai[pp], wi, xv);
                fma2(af[pp], wf, xv);
                fma2(ag[pp], wg, xv);
                fma2(ao[pp], wo, xv);
            }
        }
        #pragma unroll 5
        for (int k = 0; k < HID; k++) {
            ull wi = pack2(whh0_i[k], whh0_i[k]);
            ull wf = pack2(whh0_f[k], whh0_f[k]);
            ull wg = pack2(whh0_g[k], whh0_g[k]);
            ull wo = pack2(whh0_o[k], whh0_o[k]);
            #pragma unroll
            for (int pp = 0; pp < NPAIR; pp++) {
                ull hv = *(const ull*)&h0r[k * TSTRIDE + r0 + 2*pp];
                fma2(ai[pp], wi, hv);
                fma2(af[pp], wf, hv);
                fma2(ag[pp], wg, hv);
                fma2(ao[pp], wo, hv);
            }
        }
        #pragma unroll
        for (int pp = 0; pp < NPAIR; pp++) {
            float2 vi = unpk(ai[pp]), vf = unpk(af[pp]), vg = unpk(ag[pp]), vo = unpk(ao[pp]);
            float cx = sig_a(vf.x) * c0x[pp] + sig_a(vi.x) * tanh_a(vg.x);
            float cy = sig_a(vf.y) * c0y[pp] + sig_a(vi.y) * tanh_a(vg.y);
            c0x[pp] = cx; c0y[pp] = cy;
            float hx = sig_a(vo.x) * tanh_a(cx);
            float hy = sig_a(vo.y) * tanh_a(cy);
            *(float2*)&h0w[j * TSTRIDE + r0 + 2*pp] = make_float2(hx, hy);
        }
        __syncthreads();   // new h0 visible

        // ================= Layer 1 =================
        #pragma unroll
        for (int pp = 0; pp < NPAIR; pp++) { ai[pp]=bi1; af[pp]=bf1; ag[pp]=bg1; ao[pp]=bo1; }

        #pragma unroll 5
        for (int k = 0; k < HID; k++) {
            ull wi = pack2(wih1_i[k], wih1_i[k]);
            ull wf = pack2(wih1_f[k], wih1_f[k]);
            ull wg = pack2(wih1_g[k], wih1_g[k]);
            ull wo = pack2(wih1_o[k], wih1_o[k]);
            #pragma unroll
            for (int pp = 0; pp < NPAIR; pp++) {
                ull hv = *(const ull*)&h0w[k * TSTRIDE + r0 + 2*pp];
                fma2(ai[pp], wi, hv);
                fma2(af[pp], wf, hv);
                fma2(ag[pp], wg, hv);
                fma2(ao[pp], wo, hv);
            }
        }
        #pragma unroll 5
        for (int k = 0; k < HID; k++) {
            ull wi = pack2(whh1_i[k], whh1_i[k]);
            ull wf = pack2(whh1_f[k], whh1_f[k]);
            ull wg = pack2(whh1_g[k], whh1_g[k]);
            ull wo = pack2(whh1_o[k], whh1_o[k]);
            #pragma unroll
            for (int pp = 0; pp < NPAIR; pp++) {
                ull hv = *(const ull*)&h1r[k * TSTRIDE + r0 + 2*pp];
                fma2(ai[pp], wi, hv);
                fma2(af[pp], wf, hv);
                fma2(ag[pp], wg, hv);
                fma2(ao[pp], wo, hv);
            }
        }
        #pragma unroll
        for (int pp = 0; pp < NPAIR; pp++) {
            float2 vi = unpk(ai[pp]), vf = unpk(af[pp]), vg = unpk(ag[pp]), vo = unpk(ao[pp]);
            float cx = sig_a(vf.x) * c1x[pp] + sig_a(vi.x) * tanh_a(vg.x);
            float cy = sig_a(vf.y) * c1y[pp] + sig_a(vi.y) * tanh_a(vg.y);
            c1x[pp] = cx; c1y[pp] = cy;
            float hx = sig_a(vo.x) * tanh_a(cx);
            float hy = sig_a(vo.y) * tanh_a(cy);
            *(float2*)&h1w[j * TSTRIDE + r0 + 2*pp] = make_float2(hx, hy);
        }
        __syncthreads();   // new h1 visible

        // ---- fc1: relu(h1 @ w_fc1^T + b), 64x25 ----
        for (int task = tid; task < ROWS * FC1N; task += NTHREADS) {
            int r = task / FC1N, n = task % FC1N;
            float acc = s_bfc1[n];
            const float* wrow = &s_fc1[n * FC1_STRIDE];
            #pragma unroll 10
            for (int k = 0; k < HID; k++) acc = fmaf(wrow[k], h1w[k * TSTRIDE + r], acc);
            s_act[task] = acc > 0.0f ? acc : 0.0f;
        }
        __syncthreads();

        // ---- fc2: scalar per row ----
        if (tid < ROWS) {
            float acc = s_bfc2[0];
            const float* arow = &s_act[tid * FC1N];
            #pragma unroll
            for (int k = 0; k < FC1N; k++) acc = fmaf(s_fc2[k], arow[k], acc);
            s_delta[tid] = acc;
            out[(size_t)(brow + tid) * TSTEPS + t] = acc;
        }
        __syncthreads();
    }
}

extern "C" void kernel_launch(void* const* d_in, const int* in_sizes, int n_in,
                              void* d_out, int out_size)
{
    const float* features = (const float*)d_in[0];
    const float* w_ih0    = (const float*)d_in[1];
    const float* w_hh0    = (const float*)d_in[2];
    const float* b0       = (const float*)d_in[3];
    const float* w_ih1    = (const float*)d_in[4];
    const float* w_hh1    = (const float*)d_in[5];
    const float* b1       = (const float*)d_in[6];
    const float* w_fc1    = (const float*)d_in[7];
    const float* b_fc1    = (const float*)d_in[8];
    const float* w_fc2    = (const float*)d_in[9];
    const float* b_fc2    = (const float*)d_in[10];
    float* out = (float*)d_out;

    const int batch = in_sizes[0] / (TSTEPS * SDIM);
    const int nblocks = batch / ROWS;

    const size_t smem_bytes = SMEM_FLOATS * sizeof(float);
    cudaFuncSetAttribute(kozyra_lstm_kernel,
                         cudaFuncAttributeMaxDynamicSharedMemorySize,
                         (int)smem_bytes);

    kozyra_lstm_kernel<<<nblocks, NTHREADS, smem_bytes>>>(
        features, w_ih0, w_hh0, b0, w_ih1, w_hh1, b1,
        w_fc1, b_fc1, w_fc2, b_fc2, out);
}

// round 3
// speedup vs baseline: 2.2668x; 1.0096x over previous
#include <cuda_runtime.h>

// Problem constants
#define HID     50
#define NG      200
#define IN0     17
#define SDIM    16
#define TSTEPS  128
#define FC1N    25

// Tiling
#define ROWS      64
#define NTHREADS  800     // 25 warps: 400 slots x 2 gate-halves
#define NPAIR     4       // 4 float2 row-pairs = 8 rows per slot

// Strides (floats)
#define WI_S      17      // wih0 row stride
#define WH_S      51      // hh-type row stride
#define FC1_S     51
#define TSTRIDE   68      // state stride: 68*4=272 bytes, 16B-multiple for LDS.128

// Per-gate weight block sizes (floats), padded so block deltas == 16 (mod 32)
#define GB0       880     // wih0: 50*17=850 -> pad to 880  (880 % 32 == 16)
#define GBH       2576    // hh:   50*51=2550 -> pad to 2576 (2576 % 32 == 16)

typedef unsigned long long ull;

__device__ __forceinline__ ull pack2(float a, float b) {
    ull r; asm("mov.b64 %0,{%1,%2};" : "=l"(r) : "f"(a), "f"(b)); return r;
}
__device__ __forceinline__ float2 unpk(ull v) {
    float2 f; asm("mov.b64 {%0,%1},%2;" : "=f"(f.x), "=f"(f.y) : "l"(v)); return f;
}
__device__ __forceinline__ void fma2(ull& d, ull a, ull b) {
    asm("fma.rn.f32x2 %0,%1,%2,%0;" : "+l"(d) : "l"(a), "l"(b));
}
__device__ __forceinline__ float tanh_a(float x) {
    float y; asm("tanh.approx.f32 %0,%1;" : "=f"(y) : "f"(x)); return y;
}
__device__ __forceinline__ float sig_a(float x) {
    return fmaf(tanh_a(0.5f * x), 0.5f, 0.5f);
}

// Shared layout (float offsets)
#define OFF_WIH0   0                       // 4*880  = 3520
#define OFF_WHH0   3520                    // 4*2576 = 10304
#define OFF_WIH1   13824                   // 10304
#define OFF_WHH1   24128                   // 10304
#define OFF_FC1    34432                   // 25*51 = 1275
#define OFF_FC2    35708                   // 25
#define OFF_B0     35734                   // 200
#define OFF_B1     35934                   // 200
#define OFF_BFC1   36134                   // 25
#define OFF_BFC2   36160                   // 2
#define OFF_X      36164                   // 17*68 = 1156   (mult of 4 -> 16B aligned)
#define OFF_H0     37320                   // 2*50*68 = 6800 (double buffered)
#define OFF_H1     44120                   // 6800
#define OFF_ACT    50920                   // 64*25 = 1600
#define OFF_DELTA  52520                   // 64
#define SMEM_FLOATS 52584                  // 210336 bytes

__global__ __launch_bounds__(NTHREADS, 1)
void kozyra_lstm_kernel(const float* __restrict__ features,
                        const float* __restrict__ w_ih0, const float* __restrict__ w_hh0,
                        const float* __restrict__ b0,
                        const float* __restrict__ w_ih1, const float* __restrict__ w_hh1,
                        const float* __restrict__ b1,
                        const float* __restrict__ w_fc1, const float* __restrict__ b_fc1,
                        const float* __restrict__ w_fc2, const float* __restrict__ b_fc2,
                        float* __restrict__ out)
{
    extern __shared__ float sm[];
    float* s_fc1  = sm + OFF_FC1;
    float* s_fc2  = sm + OFF_FC2;
    float* s_b0   = sm + OFF_B0;
    float* s_b1   = sm + OFF_B1;
    float* s_bfc1 = sm + OFF_BFC1;
    float* s_bfc2 = sm + OFF_BFC2;
    float* s_x    = sm + OFF_X;      // [IN0][TSTRIDE]
    float* s_h0b  = sm + OFF_H0;     // 2 x [HID][TSTRIDE]
    float* s_h1b  = sm + OFF_H1;
    float* s_act  = sm + OFF_ACT;    // [ROWS][FC1N]
    float* s_delta= sm + OFF_DELTA;  // [ROWS]

    const int tid  = threadIdx.x;
    const int brow = blockIdx.x * ROWS;

    // ---- Stage weights: per-gate blocks, order I(0) G(1) F(2) O(3) ----
    // source gate order (PyTorch): 0=i,1=f,2=g,3=o  -> block {0:0,1:2,2:1,3:3}
    for (int idx = tid; idx < NG * IN0; idx += NTHREADS) {
        int row = idx / IN0, k = idx % IN0;
        int gate = row / HID, jj = row % HID;
        int blk = (gate == 0) ? 0 : (gate == 1) ? 2 : (gate == 2) ? 1 : 3;
        sm[OFF_WIH0 + blk * GB0 + jj * WI_S + k] = w_ih0[idx];
    }
    for (int idx = tid; idx < NG * HID; idx += NTHREADS) {
        int row = idx / HID, k = idx % HID;
        int gate = row / HID, jj = row % HID;
        int blk = (gate == 0) ? 0 : (gate == 1) ? 2 : (gate == 2) ? 1 : 3;
        int o = blk * GBH + jj * WH_S + k;
        sm[OFF_WHH0 + o] = w_hh0[idx];
        sm[OFF_WIH1 + o] = w_ih1[idx];
        sm[OFF_WHH1 + o] = w_hh1[idx];
    }
    for (int i = tid; i < FC1N * HID; i += NTHREADS) {
        int n = i / HID, k = i % HID;
        s_fc1[n * FC1_S + k] = w_fc1[i];
    }
    for (int i = tid; i < FC1N; i += NTHREADS) { s_fc2[i] = w_fc2[i]; s_bfc1[i] = b_fc1[i]; }
    for (int i = tid; i < NG;   i += NTHREADS) { s_b0[i] = b0[i]; s_b1[i] = b1[i]; }
    if (tid == 0) s_bfc2[0] = b_fc2[0];

    // ---- Init state ----
    for (int i = tid; i < 2 * HID * TSTRIDE; i += NTHREADS) { s_h0b[i] = 0.0f; s_h1b[i] = 0.0f; }
    for (int i = tid; i < ROWS; i += NTHREADS) s_delta[i] = 0.0f;
    __syncthreads();

    // ---- Thread mapping ----
    const int w    = tid >> 5;
    const int lane = tid & 31;
    const int gs   = lane >> 4;          // gate half: 0 -> (i,f), 1 -> (g,o)
    const int sub  = lane & 15;
    const int slot = w * 16 + sub;       // 0..399
    const int j    = slot % HID;
    const int rg   = slot / HID;         // 0..7
    const int r0   = rg * 8;

    // Weight row pointers: A = i|g block (blk gs), B = f|o block (blk 2+gs)
    const float* pA_ih0 = sm + OFF_WIH0 + gs * GB0 + j * WI_S;
    const float* pB_ih0 = pA_ih0 + 2 * GB0;
    const float* pA_hh0 = sm + OFF_WHH0 + gs * GBH + j * WH_S;
    const float* pB_hh0 = pA_hh0 + 2 * GBH;
    const float* pA_ih1 = sm + OFF_WIH1 + gs * GBH + j * WH_S;
    const float* pB_ih1 = pA_ih1 + 2 * GBH;
    const float* pA_hh1 = sm + OFF_WHH1 + gs * GBH + j * WH_S;
    const float* pB_hh1 = pA_hh1 + 2 * GBH;

    // Biases for my two gates (A: i or g ; B: f or o)
    const float bA0 = s_b0[(gs ? 2 : 0) * HID + j];
    const float bB0 = s_b0[(gs ? 3 : 1) * HID + j];
    const float bA1 = s_b1[(gs ? 2 : 0) * HID + j];
    const float bB1 = s_b1[(gs ? 3 : 1) * HID + j];
    const ull bpA0 = pack2(bA0, bA0), bpB0 = pack2(bB0, bB0);
    const ull bpA1 = pack2(bA1, bA1), bpB1 = pack2(bB1, bB1);

    // Cell state: this thread owns pairs p = 2*gs + {0,1}
    float cx[2][2], cy[2][2];  // [layer][lp]
    cx[0][0]=cx[0][1]=cy[0][0]=cy[0][1]=0.0f;
    cx[1][0]=cx[1][1]=cy[1][0]=cy[1][1]=0.0f;

    const float* fbase = features + (size_t)brow * (TSTEPS * SDIM);

    for (int t = 0; t < TSTEPS; t++) {
        const int pb = t & 1;
        float* h0r = s_h0b + pb * (HID * TSTRIDE);
        float* h0w = s_h0b + (pb ^ 1) * (HID * TSTRIDE);
        float* h1r = s_h1b + pb * (HID * TSTRIDE);
        float* h1w = s_h1b + (pb ^ 1) * (HID * TSTRIDE);

        // ---- Build transposed x ----
        for (int i = tid; i < ROWS * SDIM; i += NTHREADS) {
            int r = i >> 4, s = i & 15;
            s_x[s * TSTRIDE + r] = fbase[(size_t)r * (TSTEPS * SDIM) + t * SDIM + s];
        }
        if (tid < ROWS) s_x[SDIM * TSTRIDE + tid] = s_delta[tid];
        __syncthreads();

        ull a0[NPAIR], a1[NPAIR];

        // ================= Layer 0 =================
        #pragma unroll
        for (int p = 0; p < NPAIR; p++) { a0[p] = bpA0; a1[p] = bpB0; }

        #pragma unroll
        for (int k = 0; k < IN0; k++) {
            float wa = pA_ih0[k], wb = pB_ih0[k];
            ull wpa = pack2(wa, wa), wpb = pack2(wb, wb);
            ulonglong2 sv0 = *(const ulonglong2*)&s_x[k * TSTRIDE + r0];
            fma2(a0[0], wpa, sv0.x); fma2(a0[1], wpa, sv0.y);
            fma2(a1[0], wpb, sv0.x); fma2(a1[1], wpb, sv0.y);
            ulonglong2 sv1 = *(const ulonglong2*)&s_x[k * TSTRIDE + r0 + 4];
            fma2(a0[2], wpa, sv1.x); fma2(a0[3], wpa, sv1.y);
            fma2(a1[2], wpb, sv1.x); fma2(a1[3], wpb, sv1.y);
        }
        #pragma unroll 5
        for (int k = 0; k < HID; k++) {
            float wa = pA_hh0[k], wb = pB_hh0[k];
            ull wpa = pack2(wa, wa), wpb = pack2(wb, wb);
            ulonglong2 sv0 = *(const ulonglong2*)&h0r[k * TSTRIDE + r0];
            fma2(a0[0], wpa, sv0.x); fma2(a0[1], wpa, sv0.y);
            fma2(a1[0], wpb, sv0.x); fma2(a1[1], wpb, sv0.y);
            ulonglong2 sv1 = *(const ulonglong2*)&h0r[k * TSTRIDE + r0 + 4];
            fma2(a0[2], wpa, sv1.x); fma2(a0[3], wpa, sv1.y);
            fma2(a1[2], wpb, sv1.x); fma2(a1[3], wpb, sv1.y);
        }

        // ---- exchange + nonlinearity, layer 0 ----
        {
            // send my (A,B) accs for the OTHER thread's pairs; receive mine
            ull sx0 = gs ? a0[0] : a0[2];
            ull sx1 = gs ? a0[1] : a0[3];
            ull sx2 = gs ? a1[0] : a1[2];
            ull sx3 = gs ? a1[1] : a1[3];
            ull rx0 = __shfl_xor_sync(0xffffffffu, sx0, 16);
            ull rx1 = __shfl_xor_sync(0xffffffffu, sx1, 16);
            ull rx2 = __shfl_xor_sync(0xffffffffu, sx2, 16);
            ull rx3 = __shfl_xor_sync(0xffffffffu, sx3, 16);
            #pragma unroll
            for (int lp = 0; lp < 2; lp++) {
                ull gi = gs ? (lp ? rx1 : rx0) : a0[lp];
                ull gf = gs ? (lp ? rx3 : rx2) : a1[lp];
                ull gg = gs ? a0[2 + lp]       : (lp ? rx1 : rx0);
                ull go = gs ? a1[2 + lp]       : (lp ? rx3 : rx2);
                float2 vi = unpk(gi), vf = unpk(gf), vg = unpk(gg), vo = unpk(go);
                float ncx = sig_a(vf.x) * cx[0][lp] + sig_a(vi.x) * tanh_a(vg.x);
                float ncy = sig_a(vf.y) * cy[0][lp] + sig_a(vi.y) * tanh_a(vg.y);
                cx[0][lp] = ncx; cy[0][lp] = ncy;
                float hx = sig_a(vo.x) * tanh_a(ncx);
                float hy = sig_a(vo.y) * tanh_a(ncy);
                int p = 2 * gs + lp;
                *(float2*)&h0w[j * TSTRIDE + r0 + 2 * p] = make_float2(hx, hy);
            }
        }
        __syncthreads();

        // ================= Layer 1 =================
        #pragma unroll
        for (int p = 0; p < NPAIR; p++) { a0[p] = bpA1; a1[p] = bpB1; }

        #pragma unroll 5
        for (int k = 0; k < HID; k++) {
            float wa = pA_ih1[k], wb = pB_ih1[k];
            ull wpa = pack2(wa, wa), wpb = pack2(wb, wb);
            ulonglong2 sv0 = *(const ulonglong2*)&h0w[k * TSTRIDE + r0];
            fma2(a0[0], wpa, sv0.x); fma2(a0[1], wpa, sv0.y);
            fma2(a1[0], wpb, sv0.x); fma2(a1[1], wpb, sv0.y);
            ulonglong2 sv1 = *(const ulonglong2*)&h0w[k * TSTRIDE + r0 + 4];
            fma2(a0[2], wpa, sv1.x); fma2(a0[3], wpa, sv1.y);
            fma2(a1[2], wpb, sv1.x); fma2(a1[3], wpb, sv1.y);
        }
        #pragma unroll 5
        for (int k = 0; k < HID; k++) {
            float wa = pA_hh1[k], wb = pB_hh1[k];
            ull wpa = pack2(wa, wa), wpb = pack2(wb, wb);
            ulonglong2 sv0 = *(const ulonglong2*)&h1r[k * TSTRIDE + r0];
            fma2(a0[0], wpa, sv0.x); fma2(a0[1], wpa, sv0.y);
            fma2(a1[0], wpb, sv0.x); fma2(a1[1], wpb, sv0.y);
            ulonglong2 sv1 = *(const ulonglong2*)&h1r[k * TSTRIDE + r0 + 4];
            fma2(a0[2], wpa, sv1.x); fma2(a0[3], wpa, sv1.y);
            fma2(a1[2], wpb, sv1.x); fma2(a1[3], wpb, sv1.y);
        }

        // ---- exchange + nonlinearity, layer 1 ----
        {
            ull sx0 = gs ? a0[0] : a0[2];
            ull sx1 = gs ? a0[1] : a0[3];
            ull sx2 = gs ? a1[0] : a1[2];
            ull sx3 = gs ? a1[1] : a1[3];
            ull rx0 = __shfl_xor_sync(0xffffffffu, sx0, 16);
            ull rx1 = __shfl_xor_sync(0xffffffffu, sx1, 16);
            ull rx2 = __shfl_xor_sync(0xffffffffu, sx2, 16);
            ull rx3 = __shfl_xor_sync(0xffffffffu, sx3, 16);
            #pragma unroll
            for (int lp = 0; lp < 2; lp++) {
                ull gi = gs ? (lp ? rx1 : rx0) : a0[lp];
                ull gf = gs ? (lp ? rx3 : rx2) : a1[lp];
                ull gg = gs ? a0[2 + lp]       : (lp ? rx1 : rx0);
                ull go = gs ? a1[2 + lp]       : (lp ? rx3 : rx2);
                float2 vi = unpk(gi), vf = unpk(gf), vg = unpk(gg), vo = unpk(go);
                float ncx = sig_a(vf.x) * cx[1][lp] + sig_a(vi.x) * tanh_a(vg.x);
                float ncy = sig_a(vf.y) * cy[1][lp] + sig_a(vi.y) * tanh_a(vg.y);
                cx[1][lp] = ncx; cy[1][lp] = ncy;
                float hx = sig_a(vo.x) * tanh_a(ncx);
                float hy = sig_a(vo.y) * tanh_a(ncy);
                int p = 2 * gs + lp;
                *(float2*)&h1w[j * TSTRIDE + r0 + 2 * p] = make_float2(hx, hy);
            }
        }
        __syncthreads();

        // ---- fc1: relu(h1 @ w_fc1^T + b), 64x25 ----
        for (int task = tid; task < ROWS * FC1N; task += NTHREADS) {
            int r = task / FC1N, n = task % FC1N;
            float acc = s_bfc1[n];
            const float* wrow = &s_fc1[n * FC1_S];
            #pragma unroll 10
            for (int k = 0; k < HID; k++) acc = fmaf(wrow[k], h1w[k * TSTRIDE + r], acc);
            s_act[task] = acc > 0.0f ? acc : 0.0f;
        }
        __syncthreads();

        // ---- fc2 ----
        if (tid < ROWS) {
            float acc = s_bfc2[0];
            const float* arow = &s_act[tid * FC1N];
            #pragma unroll
            for (int k = 0; k < FC1N; k++) acc = fmaf(s_fc2[k], arow[k], acc);
            s_delta[tid] = acc;
            out[(size_t)(brow + tid) * TSTEPS + t] = acc;
        }
        __syncthreads();
    }
}

extern "C" void kernel_launch(void* const* d_in, const int* in_sizes, int n_in,
                              void* d_out, int out_size)
{
    const float* features = (const float*)d_in[0];
    const float* w_ih0    = (const float*)d_in[1];
    const float* w_hh0    = (const float*)d_in[2];
    const float* b0       = (const float*)d_in[3];
    const float* w_ih1    = (const float*)d_in[4];
    const float* w_hh1    = (const float*)d_in[5];
    const float* b1       = (const float*)d_in[6];
    const float* w_fc1    = (const float*)d_in[7];
    const float* b_fc1    = (const float*)d_in[8];
    const float* w_fc2    = (const float*)d_in[9];
    const float* b_fc2    = (const float*)d_in[10];
    float* out = (float*)d_out;

    const int batch = in_sizes[0] / (TSTEPS * SDIM);
    const int nblocks = batch / ROWS;

    const size_t smem_bytes = SMEM_FLOATS * sizeof(float);
    cudaFuncSetAttribute(kozyra_lstm_kernel,
                         cudaFuncAttributeMaxDynamicSharedMemorySize,
                         (int)smem_bytes);

    kozyra_lstm_kernel<<<nblocks, NTHREADS, smem_bytes>>>(
        features, w_ih0, w_hh0, b0, w_ih1, w_hh1, b1,
        w_fc1, b_fc1, w_fc2, b_fc2, out);
}

// round 4
// speedup vs baseline: 2.2706x; 1.0017x over previous
#include <cuda_runtime.h>

// Problem constants
#define HID     50
#define NG      200
#define IN0     17
#define SDIM    16
#define TSTEPS  128
#define FC1N    25

// Tiling
#define ROWS      64
#define NTHREADS  800     // 25 warps: 400 slots x 2 gate-halves
#define NPAIR     4       // 4 float2 row-pairs = 8 rows per slot

// Strides (floats)
#define WI_S      17      // wih0 row stride
#define WH_S      51      // hh-type row stride
#define FC1_S     51
#define TSTRIDE   68      // state stride: 68*4=272 bytes, 16B-multiple for LDS.128

// Per-gate weight block sizes (floats), padded so block deltas == 16 (mod 32)
#define GB0       880     // wih0: 50*17=850 -> pad to 880  (880 % 32 == 16)
#define GBH       2576    // hh:   50*51=2550 -> pad to 2576 (2576 % 32 == 16)

typedef unsigned long long ull;

__device__ __forceinline__ ull pack2(float a, float b) {
    ull r; asm("mov.b64 %0,{%1,%2};" : "=l"(r) : "f"(a), "f"(b)); return r;
}
__device__ __forceinline__ float2 unpk(ull v) {
    float2 f; asm("mov.b64 {%0,%1},%2;" : "=f"(f.x), "=f"(f.y) : "l"(v)); return f;
}
__device__ __forceinline__ void fma2(ull& d, ull a, ull b) {
    asm("fma.rn.f32x2 %0,%1,%2,%0;" : "+l"(d) : "l"(a), "l"(b));
}
__device__ __forceinline__ float tanh_a(float x) {
    float y; asm("tanh.approx.f32 %0,%1;" : "=f"(y) : "f"(x)); return y;
}
__device__ __forceinline__ float sig_a(float x) {
    return fmaf(tanh_a(0.5f * x), 0.5f, 0.5f);
}

// Shared layout (float offsets)
#define OFF_WIH0   0                       // 4*880  = 3520
#define OFF_WHH0   3520                    // 4*2576 = 10304
#define OFF_WIH1   13824                   // 10304
#define OFF_WHH1   24128                   // 10304
#define OFF_FC1    34432                   // 25*51 = 1275
#define OFF_FC2    35708                   // 25
#define OFF_B0     35734                   // 200
#define OFF_B1     35934                   // 200
#define OFF_BFC1   36134                   // 25
#define OFF_BFC2   36160                   // 2
#define OFF_X      36164                   // 17*68 = 1156   (mult of 4 -> 16B aligned)
#define OFF_H0     37320                   // 2*50*68 = 6800 (double buffered)
#define OFF_H1     44120                   // 6800
#define OFF_ACT    50920                   // 64*25 = 1600
#define OFF_DELTA  52520                   // 64
#define SMEM_FLOATS 52584                  // 210336 bytes

__global__ __launch_bounds__(NTHREADS, 1)
void kozyra_lstm_kernel(const float* __restrict__ features,
                        const float* __restrict__ w_ih0, const float* __restrict__ w_hh0,
                        const float* __restrict__ b0,
                        const float* __restrict__ w_ih1, const float* __restrict__ w_hh1,
                        const float* __restrict__ b1,
                        const float* __restrict__ w_fc1, const float* __restrict__ b_fc1,
                        const float* __restrict__ w_fc2, const float* __restrict__ b_fc2,
                        float* __restrict__ out)
{
    extern __shared__ float sm[];
    float* s_fc1  = sm + OFF_FC1;
    float* s_fc2  = sm + OFF_FC2;
    float* s_b0   = sm + OFF_B0;
    float* s_b1   = sm + OFF_B1;
    float* s_bfc1 = sm + OFF_BFC1;
    float* s_bfc2 = sm + OFF_BFC2;
    float* s_x    = sm + OFF_X;      // [IN0][TSTRIDE]
    float* s_h0b  = sm + OFF_H0;     // 2 x [HID][TSTRIDE]
    float* s_h1b  = sm + OFF_H1;
    float* s_act  = sm + OFF_ACT;    // [ROWS][FC1N]
    float* s_delta= sm + OFF_DELTA;  // [ROWS]

    const int tid  = threadIdx.x;
    const int brow = blockIdx.x * ROWS;

    // ---- Stage weights: per-gate blocks, order I(0) G(1) F(2) O(3) ----
    // source gate order (PyTorch): 0=i,1=f,2=g,3=o  -> block {0:0,1:2,2:1,3:3}
    for (int idx = tid; idx < NG * IN0; idx += NTHREADS) {
        int row = idx / IN0, k = idx % IN0;
        int gate = row / HID, jj = row % HID;
        int blk = (gate == 0) ? 0 : (gate == 1) ? 2 : (gate == 2) ? 1 : 3;
        sm[OFF_WIH0 + blk * GB0 + jj * WI_S + k] = w_ih0[idx];
    }
    for (int idx = tid; idx < NG * HID; idx += NTHREADS) {
        int row = idx / HID, k = idx % HID;
        int gate = row / HID, jj = row % HID;
        int blk = (gate == 0) ? 0 : (gate == 1) ? 2 : (gate == 2) ? 1 : 3;
        int o = blk * GBH + jj * WH_S + k;
        sm[OFF_WHH0 + o] = w_hh0[idx];
        sm[OFF_WIH1 + o] = w_ih1[idx];
        sm[OFF_WHH1 + o] = w_hh1[idx];
    }
    for (int i = tid; i < FC1N * HID; i += NTHREADS) {
        int n = i / HID, k = i % HID;
        s_fc1[n * FC1_S + k] = w_fc1[i];
    }
    for (int i = tid; i < FC1N; i += NTHREADS) { s_fc2[i] = w_fc2[i]; s_bfc1[i] = b_fc1[i]; }
    for (int i = tid; i < NG;   i += NTHREADS) { s_b0[i] = b0[i]; s_b1[i] = b1[i]; }
    if (tid == 0) s_bfc2[0] = b_fc2[0];

    // ---- Init state ----
    for (int i = tid; i < 2 * HID * TSTRIDE; i += NTHREADS) { s_h0b[i] = 0.0f; s_h1b[i] = 0.0f; }
    for (int i = tid; i < ROWS; i += NTHREADS) s_delta[i] = 0.0f;
    __syncthreads();

    // ---- Thread mapping ----
    const int w    = tid >> 5;
    const int lane = tid & 31;
    const int gs   = lane >> 4;          // gate half: 0 -> (i,f), 1 -> (g,o)
    const int sub  = lane & 15;
    const int slot = w * 16 + sub;       // 0..399
    const int j    = slot % HID;
    const int rg   = slot / HID;         // 0..7
    const int r0   = rg * 8;

    // Weight row pointers: A = i|g block (blk gs), B = f|o block (blk 2+gs)
    const float* pA_ih0 = sm + OFF_WIH0 + gs * GB0 + j * WI_S;
    const float* pB_ih0 = pA_ih0 + 2 * GB0;
    const float* pA_hh0 = sm + OFF_WHH0 + gs * GBH + j * WH_S;
    const float* pB_hh0 = pA_hh0 + 2 * GBH;
    const float* pA_ih1 = sm + OFF_WIH1 + gs * GBH + j * WH_S;
    const float* pB_ih1 = pA_ih1 + 2 * GBH;
    const float* pA_hh1 = sm + OFF_WHH1 + gs * GBH + j * WH_S;
    const float* pB_hh1 = pA_hh1 + 2 * GBH;

    // Biases for my two gates (A: i or g ; B: f or o)
    const float bA0 = s_b0[(gs ? 2 : 0) * HID + j];
    const float bB0 = s_b0[(gs ? 3 : 1) * HID + j];
    const float bA1 = s_b1[(gs ? 2 : 0) * HID + j];
    const float bB1 = s_b1[(gs ? 3 : 1) * HID + j];
    const ull bpA0 = pack2(bA0, bA0), bpB0 = pack2(bB0, bB0);
    const ull bpA1 = pack2(bA1, bA1), bpB1 = pack2(bB1, bB1);

    // Cell state: this thread owns pairs p = 2*gs + {0,1}
    float cx[2][2], cy[2][2];  // [layer][lp]
    cx[0][0]=cx[0][1]=cy[0][0]=cy[0][1]=0.0f;
    cx[1][0]=cx[1][1]=cy[1][0]=cy[1][1]=0.0f;

    const float* fbase = features + (size_t)brow * (TSTEPS * SDIM);

    for (int t = 0; t < TSTEPS; t++) {
        const int pb = t & 1;
        float* h0r = s_h0b + pb * (HID * TSTRIDE);
        float* h0w = s_h0b + (pb ^ 1) * (HID * TSTRIDE);
        float* h1r = s_h1b + pb * (HID * TSTRIDE);
        float* h1w = s_h1b + (pb ^ 1) * (HID * TSTRIDE);

        // ---- Build transposed x ----
        for (int i = tid; i < ROWS * SDIM; i += NTHREADS) {
            int r = i >> 4, s = i & 15;
            s_x[s * TSTRIDE + r] = fbase[(size_t)r * (TSTEPS * SDIM) + t * SDIM + s];
        }
        if (tid < ROWS) s_x[SDIM * TSTRIDE + tid] = s_delta[tid];
        __syncthreads();

        ull a0[NPAIR], a1[NPAIR];

        // ================= Layer 0 =================
        #pragma unroll
        for (int p = 0; p < NPAIR; p++) { a0[p] = bpA0; a1[p] = bpB0; }

        #pragma unroll
        for (int k = 0; k < IN0; k++) {
            float wa = pA_ih0[k], wb = pB_ih0[k];
            ull wpa = pack2(wa, wa), wpb = pack2(wb, wb);
            ulonglong2 sv0 = *(const ulonglong2*)&s_x[k * TSTRIDE + r0];
            fma2(a0[0], wpa, sv0.x); fma2(a0[1], wpa, sv0.y);
            fma2(a1[0], wpb, sv0.x); fma2(a1[1], wpb, sv0.y);
            ulonglong2 sv1 = *(const ulonglong2*)&s_x[k * TSTRIDE + r0 + 4];
            fma2(a0[2], wpa, sv1.x); fma2(a0[3], wpa, sv1.y);
            fma2(a1[2], wpb, sv1.x); fma2(a1[3], wpb, sv1.y);
        }
        #pragma unroll 5
        for (int k = 0; k < HID; k++) {
            float wa = pA_hh0[k], wb = pB_hh0[k];
            ull wpa = pack2(wa, wa), wpb = pack2(wb, wb);
            ulonglong2 sv0 = *(const ulonglong2*)&h0r[k * TSTRIDE + r0];
            fma2(a0[0], wpa, sv0.x); fma2(a0[1], wpa, sv0.y);
            fma2(a1[0], wpb, sv0.x); fma2(a1[1], wpb, sv0.y);
            ulonglong2 sv1 = *(const ulonglong2*)&h0r[k * TSTRIDE + r0 + 4];
            fma2(a0[2], wpa, sv1.x); fma2(a0[3], wpa, sv1.y);
            fma2(a1[2], wpb, sv1.x); fma2(a1[3], wpb, sv1.y);
        }

        // ---- exchange + nonlinearity, layer 0 ----
        {
            // send my (A,B) accs for the OTHER thread's pairs; receive mine
            ull sx0 = gs ? a0[0] : a0[2];
            ull sx1 = gs ? a0[1] : a0[3];
            ull sx2 = gs ? a1[0] : a1[2];
            ull sx3 = gs ? a1[1] : a1[3];
            ull rx0 = __shfl_xor_sync(0xffffffffu, sx0, 16);
            ull rx1 = __shfl_xor_sync(0xffffffffu, sx1, 16);
            ull rx2 = __shfl_xor_sync(0xffffffffu, sx2, 16);
            ull rx3 = __shfl_xor_sync(0xffffffffu, sx3, 16);
            #pragma unroll
            for (int lp = 0; lp < 2; lp++) {
                ull gi = gs ? (lp ? rx1 : rx0) : a0[lp];
                ull gf = gs ? (lp ? rx3 : rx2) : a1[lp];
                ull gg = gs ? a0[2 + lp]       : (lp ? rx1 : rx0);
                ull go = gs ? a1[2 + lp]       : (lp ? rx3 : rx2);
                float2 vi = unpk(gi), vf = unpk(gf), vg = unpk(gg), vo = unpk(go);
                float ncx = sig_a(vf.x) * cx[0][lp] + sig_a(vi.x) * tanh_a(vg.x);
                float ncy = sig_a(vf.y) * cy[0][lp] + sig_a(vi.y) * tanh_a(vg.y);
                cx[0][lp] = ncx; cy[0][lp] = ncy;
                float hx = sig_a(vo.x) * tanh_a(ncx);
                float hy = sig_a(vo.y) * tanh_a(ncy);
                int p = 2 * gs + lp;
                *(float2*)&h0w[j * TSTRIDE + r0 + 2 * p] = make_float2(hx, hy);
            }
        }
        __syncthreads();

        // ================= Layer 1 =================
        #pragma unroll
        for (int p = 0; p < NPAIR; p++) { a0[p] = bpA1; a1[p] = bpB1; }

        #pragma unroll 5
        for (int k = 0; k < HID; k++) {
            float wa = pA_ih1[k], wb = pB_ih1[k];
            ull wpa = pack2(wa, wa), wpb = pack2(wb, wb);
            ulonglong2 sv0 = *(const ulonglong2*)&h0w[k * TSTRIDE + r0];
            fma2(a0[0], wpa, sv0.x); fma2(a0[1], wpa, sv0.y);
            fma2(a1[0], wpb, sv0.x); fma2(a1[1], wpb, sv0.y);
            ulonglong2 sv1 = *(const ulonglong2*)&h0w[k * TSTRIDE + r0 + 4];
            fma2(a0[2], wpa, sv1.x); fma2(a0[3], wpa, sv1.y);
            fma2(a1[2], wpb, sv1.x); fma2(a1[3], wpb, sv1.y);
        }
        #pragma unroll 5
        for (int k = 0; k < HID; k++) {
            float wa = pA_hh1[k], wb = pB_hh1[k];
            ull wpa = pack2(wa, wa), wpb = pack2(wb, wb);
            ulonglong2 sv0 = *(const ulonglong2*)&h1r[k * TSTRIDE + r0];
            fma2(a0[0], wpa, sv0.x); fma2(a0[1], wpa, sv0.y);
            fma2(a1[0], wpb, sv0.x); fma2(a1[1], wpb, sv0.y);
            ulonglong2 sv1 = *(const ulonglong2*)&h1r[k * TSTRIDE + r0 + 4];
            fma2(a0[2], wpa, sv1.x); fma2(a0[3], wpa, sv1.y);
            fma2(a1[2], wpb, sv1.x); fma2(a1[3], wpb, sv1.y);
        }

        // ---- exchange + nonlinearity, layer 1 ----
        {
            ull sx0 = gs ? a0[0] : a0[2];
            ull sx1 = gs ? a0[1] : a0[3];
            ull sx2 = gs ? a1[0] : a1[2];
            ull sx3 = gs ? a1[1] : a1[3];
            ull rx0 = __shfl_xor_sync(0xffffffffu, sx0, 16);
            ull rx1 = __shfl_xor_sync(0xffffffffu, sx1, 16);
            ull rx2 = __shfl_xor_sync(0xffffffffu, sx2, 16);
            ull rx3 = __shfl_xor_sync(0xffffffffu, sx3, 16);
            #pragma unroll
            for (int lp = 0; lp < 2; lp++) {
                ull gi = gs ? (lp ? rx1 : rx0) : a0[lp];
                ull gf = gs ? (lp ? rx3 : rx2) : a1[lp];
                ull gg = gs ? a0[2 + lp]       : (lp ? rx1 : rx0);
                ull go = gs ? a1[2 + lp]       : (lp ? rx3 : rx2);
                float2 vi = unpk(gi), vf = unpk(gf), vg = unpk(gg), vo = unpk(go);
                float ncx = sig_a(vf.x) * cx[1][lp] + sig_a(vi.x) * tanh_a(vg.x);
                float ncy = sig_a(vf.y) * cy[1][lp] + sig_a(vi.y) * tanh_a(vg.y);
                cx[1][lp] = ncx; cy[1][lp] = ncy;
                float hx = sig_a(vo.x) * tanh_a(ncx);
                float hy = sig_a(vo.y) * tanh_a(ncy);
                int p = 2 * gs + lp;
                *(float2*)&h1w[j * TSTRIDE + r0 + 2 * p] = make_float2(hx, hy);
            }
        }
        __syncthreads();

        // ---- fc1: relu(h1 @ w_fc1^T + b), 64x25 ----
        for (int task = tid; task < ROWS * FC1N; task += NTHREADS) {
            int r = task / FC1N, n = task % FC1N;
            float acc = s_bfc1[n];
            const float* wrow = &s_fc1[n * FC1_S];
            #pragma unroll 10
            for (int k = 0; k < HID; k++) acc = fmaf(wrow[k], h1w[k * TSTRIDE + r], acc);
            s_act[task] = acc > 0.0f ? acc : 0.0f;
        }
        __syncthreads();

        // ---- fc2 ----
        if (tid < ROWS) {
            float acc = s_bfc2[0];
            const float* arow = &s_act[tid * FC1N];
            #pragma unroll
            for (int k = 0; k < FC1N; k++) acc = fmaf(s_fc2[k], arow[k], acc);
            s_delta[tid] = acc;
            out[(size_t)(brow + tid) * TSTEPS + t] = acc;
        }
        __syncthreads();
    }
}

extern "C" void kernel_launch(void* const* d_in, const int* in_sizes, int n_in,
                              void* d_out, int out_size)
{
    const float* features = (const float*)d_in[0];
    const float* w_ih0    = (const float*)d_in[1];
    const float* w_hh0    = (const float*)d_in[2];
    const float* b0       = (const float*)d_in[3];
    const float* w_ih1    = (const float*)d_in[4];
    const float* w_hh1    = (const float*)d_in[5];
    const float* b1       = (const float*)d_in[6];
    const float* w_fc1    = (const float*)d_in[7];
    const float* b_fc1    = (const float*)d_in[8];
    const float* w_fc2    = (const float*)d_in[9];
    const float* b_fc2    = (const float*)d_in[10];
    float* out = (float*)d_out;

    const int batch = in_sizes[0] / (TSTEPS * SDIM);
    const int nblocks = batch / ROWS;

    const size_t smem_bytes = SMEM_FLOATS * sizeof(float);
    cudaFuncSetAttribute(kozyra_lstm_kernel,
                         cudaFuncAttributeMaxDynamicSharedMemorySize,
                         (int)smem_bytes);

    kozyra_lstm_kernel<<<nblocks, NTHREADS, smem_bytes>>>(
        features, w_ih0, w_hh0, b0, w_ih1, w_hh1, b1,
        w_fc1, b_fc1, w_fc2, b_fc2, out);
}

// round 5
// speedup vs baseline: 2.5014x; 1.1017x over previous
#include <cuda_runtime.h>

// Problem constants
#define HID     50
#define NG      200
#define IN0     17
#define SDIM    16
#define TSTEPS  128
#define FC1N    25

// Tiling
#define ROWS      64
#define NTHREADS  800     // 25 warps
#define NPAIR     4

// Strides (floats)
#define WI_S      17
#define WH_S      51
#define FC1_S     51
#define TSTRIDE   68      // 272B rows, 16B-aligned

// Per-gate weight blocks, deltas == 16 (mod 32) banks for half-warp complement
#define GB0       880
#define GBH       2576

typedef unsigned long long ull;

__device__ __forceinline__ ull pack2(float a, float b) {
    ull r; asm("mov.b64 %0,{%1,%2};" : "=l"(r) : "f"(a), "f"(b)); return r;
}
__device__ __forceinline__ float2 unpk(ull v) {
    float2 f; asm("mov.b64 {%0,%1},%2;" : "=f"(f.x), "=f"(f.y) : "l"(v)); return f;
}
__device__ __forceinline__ void fma2(ull& d, ull a, ull b) {
    asm("fma.rn.f32x2 %0,%1,%2,%0;" : "+l"(d) : "l"(a), "l"(b));
}
__device__ __forceinline__ void add2(ull& d, ull a) {
    asm("add.rn.f32x2 %0,%0,%1;" : "+l"(d) : "l"(a));
}
__device__ __forceinline__ float tanh_a(float x) {
    float y; asm("tanh.approx.f32 %0,%1;" : "=f"(y) : "f"(x)); return y;
}
__device__ __forceinline__ float sig_a(float x) {
    return fmaf(tanh_a(0.5f * x), 0.5f, 0.5f);
}

// Shared layout (float offsets)
#define OFF_WIH0   0                       // 4*880  = 3520
#define OFF_WHH0   3520                    // 4*2576 = 10304
#define OFF_WIH1   13824
#define OFF_WHH1   24128
#define OFF_FC1    34432                   // 25*51 = 1275
#define OFF_FC2    35708                   // 25
#define OFF_B0     35734                   // 200
#define OFF_B1     35934                   // 200
#define OFF_BFC1   36134                   // 25
#define OFF_BFC2   36160                   // 2
#define OFF_X      36164                   // 17*68 = 1156
#define OFF_H0     37320                   // 2*50*68 = 6800
#define OFF_H1     44120                   // 6800
#define SMEM_FLOATS 50920                  // 203680 bytes

__global__ __launch_bounds__(NTHREADS, 1)
void kozyra_lstm_kernel(const float* __restrict__ features,
                        const float* __restrict__ w_ih0, const float* __restrict__ w_hh0,
                        const float* __restrict__ b0,
                        const float* __restrict__ w_ih1, const float* __restrict__ w_hh1,
                        const float* __restrict__ b1,
                        const float* __restrict__ w_fc1, const float* __restrict__ b_fc1,
                        const float* __restrict__ w_fc2, const float* __restrict__ b_fc2,
                        float* __restrict__ out)
{
    extern __shared__ float sm[];
    float* s_fc1  = sm + OFF_FC1;
    float* s_fc2  = sm + OFF_FC2;
    float* s_b0   = sm + OFF_B0;
    float* s_b1   = sm + OFF_B1;
    float* s_bfc1 = sm + OFF_BFC1;
    float* s_bfc2 = sm + OFF_BFC2;
    float* s_x    = sm + OFF_X;      // [IN0][TSTRIDE]
    float* s_h0b  = sm + OFF_H0;     // 2 x [HID][TSTRIDE]
    float* s_h1b  = sm + OFF_H1;

    const int tid  = threadIdx.x;
    const int brow = blockIdx.x * ROWS;

    // ---- Stage weights: per-gate blocks, order I(0) G(1) F(2) O(3) ----
    for (int idx = tid; idx < NG * IN0; idx += NTHREADS) {
        int row = idx / IN0, k = idx % IN0;
        int gate = row / HID, jj = row % HID;
        int blk = (gate == 0) ? 0 : (gate == 1) ? 2 : (gate == 2) ? 1 : 3;
        sm[OFF_WIH0 + blk * GB0 + jj * WI_S + k] = w_ih0[idx];
    }
    for (int idx = tid; idx < NG * HID; idx += NTHREADS) {
        int row = idx / HID, k = idx % HID;
        int gate = row / HID, jj = row % HID;
        int blk = (gate == 0) ? 0 : (gate == 1) ? 2 : (gate == 2) ? 1 : 3;
        int o = blk * GBH + jj * WH_S + k;
        sm[OFF_WHH0 + o] = w_hh0[idx];
        sm[OFF_WIH1 + o] = w_ih1[idx];
        sm[OFF_WHH1 + o] = w_hh1[idx];
    }
    for (int i = tid; i < FC1N * HID; i += NTHREADS) {
        int n = i / HID, k = i % HID;
        s_fc1[n * FC1_S + k] = w_fc1[i];
    }
    for (int i = tid; i < FC1N; i += NTHREADS) { s_fc2[i] = w_fc2[i]; s_bfc1[i] = b_fc1[i]; }
    for (int i = tid; i < NG;   i += NTHREADS) { s_b0[i] = b0[i]; s_b1[i] = b1[i]; }
    if (tid == 0) s_bfc2[0] = b_fc2[0];

    // ---- Init state + x for t=0 ----
    for (int i = tid; i < 2 * HID * TSTRIDE; i += NTHREADS) { s_h0b[i] = 0.0f; s_h1b[i] = 0.0f; }
    const float* fbase = features + (size_t)brow * (TSTEPS * SDIM);
    for (int i = tid; i < ROWS * SDIM; i += NTHREADS) {
        int r = i >> 4, s = i & 15;
        s_x[s * TSTRIDE + r] = fbase[(size_t)r * (TSTEPS * SDIM) + s];
    }
    if (tid < ROWS) s_x[SDIM * TSTRIDE + tid] = 0.0f;
    __syncthreads();

    // ---- Thread mapping: straddle-free warps ----
    const int w    = tid >> 5;
    const int lane = tid & 31;
    const int gs   = lane >> 4;          // 0 -> (i,f), 1 -> (g,o)
    const int sub  = lane & 15;
    int rg, j;
    if (w < 24) { rg = w / 3; j = (w % 3) * 16 + sub; }
    else        { rg = sub >> 1; j = 48 + (sub & 1); }
    const int r0 = rg * 8;

    const float* pA_ih0 = sm + OFF_WIH0 + gs * GB0 + j * WI_S;
    const float* pB_ih0 = pA_ih0 + 2 * GB0;
    const float* pA_hh0 = sm + OFF_WHH0 + gs * GBH + j * WH_S;
    const float* pB_hh0 = pA_hh0 + 2 * GBH;
    const float* pA_ih1 = sm + OFF_WIH1 + gs * GBH + j * WH_S;
    const float* pB_ih1 = pA_ih1 + 2 * GBH;
    const float* pA_hh1 = sm + OFF_WHH1 + gs * GBH + j * WH_S;
    const float* pB_hh1 = pA_hh1 + 2 * GBH;

    const float bA0 = s_b0[(gs ? 2 : 0) * HID + j];
    const float bB0 = s_b0[(gs ? 3 : 1) * HID + j];
    const float bA1 = s_b1[(gs ? 2 : 0) * HID + j];
    const float bB1 = s_b1[(gs ? 3 : 1) * HID + j];
    const ull bpA0 = pack2(bA0, bA0), bpB0 = pack2(bB0, bB0);
    const ull bpA1 = pack2(bA1, bA1), bpB1 = pack2(bB1, bB1);

    float cx[2][2], cy[2][2];
    cx[0][0]=cx[0][1]=cy[0][0]=cy[0][1]=0.0f;
    cx[1][0]=cx[1][1]=cy[1][0]=cy[1][1]=0.0f;

    for (int t = 0; t < TSTEPS; t++) {
        const int pb = t & 1;
        float* h0r = s_h0b + pb * (HID * TSTRIDE);
        float* h0w = s_h0b + (pb ^ 1) * (HID * TSTRIDE);
        float* h1r = s_h1b + pb * (HID * TSTRIDE);
        float* h1w = s_h1b + (pb ^ 1) * (HID * TSTRIDE);

        ull a0[NPAIR], a1[NPAIR];

        // ================= Layer 0 =================
        #pragma unroll
        for (int p = 0; p < NPAIR; p++) { a0[p] = bpA0; a1[p] = bpB0; }

        #pragma unroll
        for (int k = 0; k < IN0; k++) {
            float wa = pA_ih0[k], wb = pB_ih0[k];
            ull wpa = pack2(wa, wa), wpb = pack2(wb, wb);
            ulonglong2 sv0 = *(const ulonglong2*)&s_x[k * TSTRIDE + r0];
            fma2(a0[0], wpa, sv0.x); fma2(a0[1], wpa, sv0.y);
            fma2(a1[0], wpb, sv0.x); fma2(a1[1], wpb, sv0.y);
            ulonglong2 sv1 = *(const ulonglong2*)&s_x[k * TSTRIDE + r0 + 4];
            fma2(a0[2], wpa, sv1.x); fma2(a0[3], wpa, sv1.y);
            fma2(a1[2], wpb, sv1.x); fma2(a1[3], wpb, sv1.y);
        }
        #pragma unroll 5
        for (int k = 0; k < HID; k++) {
            float wa = pA_hh0[k], wb = pB_hh0[k];
            ull wpa = pack2(wa, wa), wpb = pack2(wb, wb);
            ulonglong2 sv0 = *(const ulonglong2*)&h0r[k * TSTRIDE + r0];
            fma2(a0[0], wpa, sv0.x); fma2(a0[1], wpa, sv0.y);
            fma2(a1[0], wpb, sv0.x); fma2(a1[1], wpb, sv0.y);
            ulonglong2 sv1 = *(const ulonglong2*)&h0r[k * TSTRIDE + r0 + 4];
            fma2(a0[2], wpa, sv1.x); fma2(a0[3], wpa, sv1.y);
            fma2(a1[2], wpb, sv1.x); fma2(a1[3], wpb, sv1.y);
        }

        {   // exchange + nonlinearity, layer 0
            ull sx0 = gs ? a0[0] : a0[2];
            ull sx1 = gs ? a0[1] : a0[3];
            ull sx2 = gs ? a1[0] : a1[2];
            ull sx3 = gs ? a1[1] : a1[3];
            ull rx0 = __shfl_xor_sync(0xffffffffu, sx0, 16);
            ull rx1 = __shfl_xor_sync(0xffffffffu, sx1, 16);
            ull rx2 = __shfl_xor_sync(0xffffffffu, sx2, 16);
            ull rx3 = __shfl_xor_sync(0xffffffffu, sx3, 16);
            #pragma unroll
            for (int lp = 0; lp < 2; lp++) {
                ull gi = gs ? (lp ? rx1 : rx0) : a0[lp];
                ull gf = gs ? (lp ? rx3 : rx2) : a1[lp];
                ull gg = gs ? a0[2 + lp]       : (lp ? rx1 : rx0);
                ull go = gs ? a1[2 + lp]       : (lp ? rx3 : rx2);
                float2 vi = unpk(gi), vf = unpk(gf), vg = unpk(gg), vo = unpk(go);
                float ncx = sig_a(vf.x) * cx[0][lp] + sig_a(vi.x) * tanh_a(vg.x);
                float ncy = sig_a(vf.y) * cy[0][lp] + sig_a(vi.y) * tanh_a(vg.y);
                cx[0][lp] = ncx; cy[0][lp] = ncy;
                float hx = sig_a(vo.x) * tanh_a(ncx);
                float hy = sig_a(vo.y) * tanh_a(ncy);
                int p = 2 * gs + lp;
                *(float2*)&h0w[j * TSTRIDE + r0 + 2 * p] = make_float2(hx, hy);
            }
        }
        __syncthreads();   // SYNC_A: h0 visible

        // ================= Layer 1 =================
        #pragma unroll
        for (int p = 0; p < NPAIR; p++) { a0[p] = bpA1; a1[p] = bpB1; }

        #pragma unroll 5
        for (int k = 0; k < HID; k++) {
            float wa = pA_ih1[k], wb = pB_ih1[k];
            ull wpa = pack2(wa, wa), wpb = pack2(wb, wb);
            ulonglong2 sv0 = *(const ulonglong2*)&h0w[k * TSTRIDE + r0];
            fma2(a0[0], wpa, sv0.x); fma2(a0[1], wpa, sv0.y);
            fma2(a1[0], wpb, sv0.x); fma2(a1[1], wpb, sv0.y);
            ulonglong2 sv1 = *(const ulonglong2*)&h0w[k * TSTRIDE + r0 + 4];
            fma2(a0[2], wpa, sv1.x); fma2(a0[3], wpa, sv1.y);
            fma2(a1[2], wpb, sv1.x); fma2(a1[3], wpb, sv1.y);
        }
        #pragma unroll 5
        for (int k = 0; k < HID; k++) {
            float wa = pA_hh1[k], wb = pB_hh1[k];
            ull wpa = pack2(wa, wa), wpb = pack2(wb, wb);
            ulonglong2 sv0 = *(const ulonglong2*)&h1r[k * TSTRIDE + r0];
            fma2(a0[0], wpa, sv0.x); fma2(a0[1], wpa, sv0.y);
            fma2(a1[0], wpb, sv0.x); fma2(a1[1], wpb, sv0.y);
            ulonglong2 sv1 = *(const ulonglong2*)&h1r[k * TSTRIDE + r0 + 4];
            fma2(a0[2], wpa, sv1.x); fma2(a0[3], wpa, sv1.y);
            fma2(a1[2], wpb, sv1.x); fma2(a1[3], wpb, sv1.y);
        }

        {   // exchange + nonlinearity, layer 1
            ull sx0 = gs ? a0[0] : a0[2];
            ull sx1 = gs ? a0[1] : a0[3];
            ull sx2 = gs ? a1[0] : a1[2];
            ull sx3 = gs ? a1[1] : a1[3];
            ull rx0 = __shfl_xor_sync(0xffffffffu, sx0, 16);
            ull rx1 = __shfl_xor_sync(0xffffffffu, sx1, 16);
            ull rx2 = __shfl_xor_sync(0xffffffffu, sx2, 16);
            ull rx3 = __shfl_xor_sync(0xffffffffu, sx3, 16);
            #pragma unroll
            for (int lp = 0; lp < 2; lp++) {
                ull gi = gs ? (lp ? rx1 : rx0) : a0[lp];
                ull gf = gs ? (lp ? rx3 : rx2) : a1[lp];
                ull gg = gs ? a0[2 + lp]       : (lp ? rx1 : rx0);
                ull go = gs ? a1[2 + lp]       : (lp ? rx3 : rx2);
                float2 vi = unpk(gi), vf = unpk(gf), vg = unpk(gg), vo = unpk(go);
                float ncx = sig_a(vf.x) * cx[1][lp] + sig_a(vi.x) * tanh_a(vg.x);
                float ncy = sig_a(vf.y) * cy[1][lp] + sig_a(vi.y) * tanh_a(vg.y);
                cx[1][lp] = ncx; cy[1][lp] = ncy;
                float hx = sig_a(vo.x) * tanh_a(ncx);
                float hy = sig_a(vo.y) * tanh_a(ncy);
                int p = 2 * gs + lp;
                *(float2*)&h1w[j * TSTRIDE + r0 + 2 * p] = make_float2(hx, hy);
            }
        }
        __syncthreads();   // SYNC_B: h1 visible

        // ========= fc1+fc2 fused + x-build for t+1 =========
        // feature prefetch (gmem, issue early)
        float f0 = 0.0f, f1 = 0.0f;
        const bool has_next = (t + 1 < TSTEPS);
        if (has_next) {
            int r = tid >> 4, s = tid & 15;
            f0 = fbase[(size_t)r * (TSTEPS * SDIM) + (size_t)(t + 1) * SDIM + s];
            if (tid < 224) {
                int i1 = tid + NTHREADS;
                f1 = fbase[(size_t)(i1 >> 4) * (TSTEPS * SDIM) + (size_t)(t + 1) * SDIM + (i1 & 15)];
            }
        }

        // fc tasks: warp w -> row-pair w; warps 0..6 also row-pair 25+w
        #pragma unroll
        for (int task = 0; task < 2; task++) {
            if (task == 1 && w >= 7) break;
            int rp = (task == 0) ? w : (25 + w);
            ull acc = 0ULL;
            if (lane < FC1N) {
                acc = pack2(s_bfc1[lane], s_bfc1[lane]);
                const float* wr = &s_fc1[lane * FC1_S];
                #pragma unroll 10
                for (int k = 0; k < HID; k++) {
                    float wv = wr[k];
                    ull hv = *(const ull*)&h1w[k * TSTRIDE + 2 * rp];
                    fma2(acc, pack2(wv, wv), hv);
                }
                float2 a = unpk(acc);
                float sc = s_fc2[lane];
                a.x = fmaxf(a.x, 0.0f) * sc;
                a.y = fmaxf(a.y, 0.0f) * sc;
                acc = pack2(a.x, a.y);
            }
            #pragma unroll
            for (int off = 16; off > 0; off >>= 1)
                add2(acc, __shfl_down_sync(0xffffffffu, acc, off));
            if (lane == 0) {
                float2 d = unpk(acc);
                float bb = s_bfc2[0];
                d.x += bb; d.y += bb;
                *(float2*)&s_x[SDIM * TSTRIDE + 2 * rp] = d;   // delta -> next x
                out[(size_t)(brow + 2 * rp)     * TSTEPS + t] = d.x;
                out[(size_t)(brow + 2 * rp + 1) * TSTEPS + t] = d.y;
            }
        }

        // store prefetched features for t+1
        if (has_next) {
            int r = tid >> 4, s = tid & 15;
            s_x[s * TSTRIDE + r] = f0;
            if (tid < 224) {
                int i1 = tid + NTHREADS;
                s_x[(i1 & 15) * TSTRIDE + (i1 >> 4)] = f1;
            }
        }
        __syncthreads();   // SYNC_C: delta + x(t+1) visible
    }
}

extern "C" void kernel_launch(void* const* d_in, const int* in_sizes, int n_in,
                              void* d_out, int out_size)
{
    const float* features = (const float*)d_in[0];
    const float* w_ih0    = (const float*)d_in[1];
    const float* w_hh0    = (const float*)d_in[2];
    const float* b0       = (const float*)d_in[3];
    const float* w_ih1    = (const float*)d_in[4];
    const float* w_hh1    = (const float*)d_in[5];
    const float* b1       = (const float*)d_in[6];
    const float* w_fc1    = (const float*)d_in[7];
    const float* b_fc1    = (const float*)d_in[8];
    const float* w_fc2    = (const float*)d_in[9];
    const float* b_fc2    = (const float*)d_in[10];
    float* out = (float*)d_out;

    const int batch = in_sizes[0] / (TSTEPS * SDIM);
    const int nblocks = batch / ROWS;

    const size_t smem_bytes = SMEM_FLOATS * sizeof(float);
    cudaFuncSetAttribute(kozyra_lstm_kernel,
                         cudaFuncAttributeMaxDynamicSharedMemorySize,
                         (int)smem_bytes);

    kozyra_lstm_kernel<<<nblocks, NTHREADS, smem_bytes>>>(
        features, w_ih0, w_hh0, b0, w_ih1, w_hh1, b1,
        w_fc1, b_fc1, w_fc2, b_fc2, out);
}